// round 1
// baseline (speedup 1.0000x reference)
#include <cuda_runtime.h>

// Problem dims
#define Bdim 4
#define Tdim 2048
#define Cdim 1024
#define Hdim 16
#define Rdim 256
#define Sdim 64
#define Ddim 64
#define Mrows (Bdim * Tdim)   // 8192
#define ATTN_SCALE 0.125f     // 1/sqrt(64)

// Scratch (no allocation allowed -> device globals)
__device__ float g_latent[Mrows * Rdim];                 //  8 MB
__device__ float g_q[Bdim * Hdim * Tdim * Sdim];         // 32 MB
__device__ float g_k[Bdim * Hdim * Tdim * Sdim];         // 32 MB
__device__ float g_v[Bdim * Hdim * Tdim * Ddim];         // 32 MB  [B,H,T,D]
__device__ float g_y[Mrows * Cdim];                      // 32 MB

// ---------------------------------------------------------------------------
// Generic NT SGEMM: C[M,N] = A[M,K] * B[N,K]^T (+bias)
// BM=128, BN=64, BK=16, 256 threads, 8x4 per thread.
// LAYOUT 0: row-major [M,N].  LAYOUT 1: remap to V layout [B,H,T,D]
// ---------------------------------------------------------------------------
template <int LAYOUT, bool HAS_BIAS>
__global__ void __launch_bounds__(256)
gemm_nt(const float* __restrict__ A, const float* __restrict__ Bw,
        const float* __restrict__ bias, float* __restrict__ C,
        int Ndim_, int Kdim_)
{
    __shared__ float As[16][128];   // transposed: As[k][m]
    __shared__ float Bs[16][64];    // transposed: Bs[k][n]

    const int bm = blockIdx.y * 128;
    const int bn = blockIdx.x * 64;
    const int tid = threadIdx.x;
    const int tx = tid & 15;        // 0..15 -> n
    const int ty = tid >> 4;        // 0..15 -> m

    float acc[8][4];
#pragma unroll
    for (int i = 0; i < 8; i++)
#pragma unroll
        for (int j = 0; j < 4; j++) acc[i][j] = 0.f;

    // A tile: 128 rows x 16 cols = 512 float4 -> 2 per thread
    // B tile:  64 rows x 16 cols = 256 float4 -> 1 per thread
    const int br = tid >> 2;        // 0..63
    const int bc4 = tid & 3;        // 0..3

    for (int k0 = 0; k0 < Kdim_; k0 += 16) {
#pragma unroll
        for (int i = 0; i < 2; i++) {
            int f = tid + i * 256;
            int ar = f >> 2;        // 0..127
            int ac4 = f & 3;
            float4 a4 = *(const float4*)&A[(size_t)(bm + ar) * Kdim_ + k0 + ac4 * 4];
            As[ac4 * 4 + 0][ar] = a4.x;
            As[ac4 * 4 + 1][ar] = a4.y;
            As[ac4 * 4 + 2][ar] = a4.z;
            As[ac4 * 4 + 3][ar] = a4.w;
        }
        {
            float4 b4 = *(const float4*)&Bw[(size_t)(bn + br) * Kdim_ + k0 + bc4 * 4];
            Bs[bc4 * 4 + 0][br] = b4.x;
            Bs[bc4 * 4 + 1][br] = b4.y;
            Bs[bc4 * 4 + 2][br] = b4.z;
            Bs[bc4 * 4 + 3][br] = b4.w;
        }
        __syncthreads();

#pragma unroll
        for (int kk = 0; kk < 16; kk++) {
            float ar[8], brv[4];
#pragma unroll
            for (int i = 0; i < 8; i++) ar[i] = As[kk][ty * 8 + i];
#pragma unroll
            for (int j = 0; j < 4; j++) brv[j] = Bs[kk][tx * 4 + j];
#pragma unroll
            for (int i = 0; i < 8; i++)
#pragma unroll
                for (int j = 0; j < 4; j++)
                    acc[i][j] = fmaf(ar[i], brv[j], acc[i][j]);
        }
        __syncthreads();
    }

#pragma unroll
    for (int i = 0; i < 8; i++) {
        int m = bm + ty * 8 + i;
#pragma unroll
        for (int j = 0; j < 4; j++) {
            int n = bn + tx * 4 + j;
            float val = acc[i][j];
            if (HAS_BIAS) val += bias[n];
            if (LAYOUT == 0) {
                C[(size_t)m * Ndim_ + n] = val;
            } else {
                int b = m / Tdim, t = m % Tdim;
                int h = n / Ddim, d = n % Ddim;
                C[(((size_t)b * Hdim + h) * Tdim + t) * Ddim + d] = val;
            }
        }
    }
}

// ---------------------------------------------------------------------------
// Fused q/k: per head h,  q = latent[8192,256] * U_h[256,64]  (NN)
//                          k = latent[8192,256] * V_h[256,64]  (NN)
// Shares the latent smem tile between both products.
// ---------------------------------------------------------------------------
__global__ void __launch_bounds__(256)
gemm_qk(const float* __restrict__ latent, const float* __restrict__ U,
        const float* __restrict__ Vf, float* __restrict__ q, float* __restrict__ k)
{
    __shared__ float As[16][64];    // latent transposed: As[r][m]
    __shared__ float Us[16][64];    // Us[r][s]
    __shared__ float Vs[16][64];

    const int h = blockIdx.y;
    const int bm = blockIdx.x * 64;
    const int tid = threadIdx.x;
    const int tx = tid & 15;
    const int ty = tid >> 4;

    const float* Uh = U + (size_t)h * Rdim * Sdim;
    const float* Vh = Vf + (size_t)h * Rdim * Sdim;

    float accq[4][4], acck[4][4];
#pragma unroll
    for (int i = 0; i < 4; i++)
#pragma unroll
        for (int j = 0; j < 4; j++) { accq[i][j] = 0.f; acck[i][j] = 0.f; }

    const int lr = tid >> 2, lc4 = tid & 3;     // latent tile load
    const int ur = tid >> 4, uc4 = tid & 15;    // factor tile load

    for (int r0 = 0; r0 < Rdim; r0 += 16) {
        float4 a4 = *(const float4*)&latent[(size_t)(bm + lr) * Rdim + r0 + lc4 * 4];
        As[lc4 * 4 + 0][lr] = a4.x;
        As[lc4 * 4 + 1][lr] = a4.y;
        As[lc4 * 4 + 2][lr] = a4.z;
        As[lc4 * 4 + 3][lr] = a4.w;
        *(float4*)&Us[ur][uc4 * 4] = *(const float4*)&Uh[(size_t)(r0 + ur) * Sdim + uc4 * 4];
        *(float4*)&Vs[ur][uc4 * 4] = *(const float4*)&Vh[(size_t)(r0 + ur) * Sdim + uc4 * 4];
        __syncthreads();

#pragma unroll
        for (int kk = 0; kk < 16; kk++) {
            float ar[4], uq[4], uk[4];
#pragma unroll
            for (int i = 0; i < 4; i++) ar[i] = As[kk][ty * 4 + i];
#pragma unroll
            for (int j = 0; j < 4; j++) { uq[j] = Us[kk][tx * 4 + j]; uk[j] = Vs[kk][tx * 4 + j]; }
#pragma unroll
            for (int i = 0; i < 4; i++)
#pragma unroll
                for (int j = 0; j < 4; j++) {
                    accq[i][j] = fmaf(ar[i], uq[j], accq[i][j]);
                    acck[i][j] = fmaf(ar[i], uk[j], acck[i][j]);
                }
        }
        __syncthreads();
    }

#pragma unroll
    for (int i = 0; i < 4; i++) {
        int m = bm + ty * 4 + i;
        int b = m / Tdim, t = m % Tdim;
        size_t base = (((size_t)b * Hdim + h) * Tdim + t) * Sdim + tx * 4;
        *(float4*)&q[base] = make_float4(accq[i][0], accq[i][1], accq[i][2], accq[i][3]);
        *(float4*)&k[base] = make_float4(acck[i][0], acck[i][1], acck[i][2], acck[i][3]);
    }
}

// ---------------------------------------------------------------------------
// Causal flash attention, fp32.  64x64 tiles, online softmax.
// q,k: [B,H,T,64]; v: [B,H,T,64]; y out: [B,T,C] at column h*64.
// Smem: Qst(16K) + KPs(16K, K tile reused as P) + Vs(16K) = 48 KB static.
// ---------------------------------------------------------------------------
__global__ void __launch_bounds__(256)
flash_attn(const float* __restrict__ q, const float* __restrict__ k,
           const float* __restrict__ v, float* __restrict__ y)
{
    __shared__ float Qst[64 * 64];  // [s][m] transposed
    __shared__ float KPs[64 * 64];  // phase1: Kst [s][u]; phase2: P [r][u]
    __shared__ float Vs[64 * 64];   // [u][d]

    const int bh = blockIdx.y;
    const int b = bh / Hdim, h = bh % Hdim;
    const int q0 = blockIdx.x * 64;
    const float* Q = q + (size_t)bh * Tdim * Sdim;
    const float* K = k + (size_t)bh * Tdim * Sdim;
    const float* V = v + (size_t)bh * Tdim * Ddim;

    const int tid = threadIdx.x;
    const int tx = tid & 15;
    const int ty = tid >> 4;

    // Load Q tile transposed
#pragma unroll
    for (int i = 0; i < 4; i++) {
        int f = tid + i * 256;
        int r = f >> 4, c4 = f & 15;
        float4 v4 = *(const float4*)&Q[(size_t)(q0 + r) * Sdim + c4 * 4];
        Qst[(c4 * 4 + 0) * 64 + r] = v4.x;
        Qst[(c4 * 4 + 1) * 64 + r] = v4.y;
        Qst[(c4 * 4 + 2) * 64 + r] = v4.z;
        Qst[(c4 * 4 + 3) * 64 + r] = v4.w;
    }

    float o[4][4];
    float mrow[4], lrow[4];
#pragma unroll
    for (int i = 0; i < 4; i++) {
        mrow[i] = -1e30f; lrow[i] = 0.f;
#pragma unroll
        for (int j = 0; j < 4; j++) o[i][j] = 0.f;
    }
    __syncthreads();

    const int nkt = blockIdx.x + 1;
    for (int kt = 0; kt < nkt; kt++) {
        const int k0 = kt * 64;
        // Load K tile (transposed) + V tile (natural)
#pragma unroll
        for (int i = 0; i < 4; i++) {
            int f = tid + i * 256;
            int r = f >> 4, c4 = f & 15;
            float4 kv = *(const float4*)&K[(size_t)(k0 + r) * Sdim + c4 * 4];
            KPs[(c4 * 4 + 0) * 64 + r] = kv.x;
            KPs[(c4 * 4 + 1) * 64 + r] = kv.y;
            KPs[(c4 * 4 + 2) * 64 + r] = kv.z;
            KPs[(c4 * 4 + 3) * 64 + r] = kv.w;
            *(float4*)&Vs[r * 64 + c4 * 4] = *(const float4*)&V[(size_t)(k0 + r) * Ddim + c4 * 4];
        }
        __syncthreads();

        // S = Q * K^T
        float s[4][4];
#pragma unroll
        for (int i = 0; i < 4; i++)
#pragma unroll
            for (int j = 0; j < 4; j++) s[i][j] = 0.f;
#pragma unroll
        for (int kk = 0; kk < 64; kk++) {
            float qa[4], kb[4];
#pragma unroll
            for (int i = 0; i < 4; i++) qa[i] = Qst[kk * 64 + ty * 4 + i];
#pragma unroll
            for (int j = 0; j < 4; j++) kb[j] = KPs[kk * 64 + tx * 4 + j];
#pragma unroll
            for (int i = 0; i < 4; i++)
#pragma unroll
                for (int j = 0; j < 4; j++)
                    s[i][j] = fmaf(qa[i], kb[j], s[i][j]);
        }
        __syncthreads();   // done reading KPs as K -> can be overwritten as P below

        const bool diag = (kt == blockIdx.x);
#pragma unroll
        for (int i = 0; i < 4; i++)
#pragma unroll
            for (int j = 0; j < 4; j++) {
                s[i][j] *= ATTN_SCALE;
                if (diag && (k0 + tx * 4 + j) > (q0 + ty * 4 + i)) s[i][j] = -1e30f;
            }

        // Online softmax per row (row group = 16 consecutive lanes)
#pragma unroll
        for (int i = 0; i < 4; i++) {
            float mx = fmaxf(fmaxf(s[i][0], s[i][1]), fmaxf(s[i][2], s[i][3]));
#pragma unroll
            for (int off = 8; off >= 1; off >>= 1)
                mx = fmaxf(mx, __shfl_xor_sync(0xffffffffu, mx, off));
            float mnew = fmaxf(mrow[i], mx);
            float alpha = __expf(mrow[i] - mnew);
            mrow[i] = mnew;
            float rs = 0.f;
#pragma unroll
            for (int j = 0; j < 4; j++) { s[i][j] = __expf(s[i][j] - mnew); rs += s[i][j]; }
#pragma unroll
            for (int off = 8; off >= 1; off >>= 1)
                rs += __shfl_xor_sync(0xffffffffu, rs, off);
            lrow[i] = lrow[i] * alpha + rs;
#pragma unroll
            for (int j = 0; j < 4; j++) o[i][j] *= alpha;
        }

        // Store P into KPs
#pragma unroll
        for (int i = 0; i < 4; i++)
            *(float4*)&KPs[(ty * 4 + i) * 64 + tx * 4] =
                make_float4(s[i][0], s[i][1], s[i][2], s[i][3]);
        __syncthreads();

        // O += P * V
#pragma unroll
        for (int kk = 0; kk < 64; kk++) {
            float pv[4], vv[4];
#pragma unroll
            for (int i = 0; i < 4; i++) pv[i] = KPs[(ty * 4 + i) * 64 + kk];
#pragma unroll
            for (int j = 0; j < 4; j++) vv[j] = Vs[kk * 64 + tx * 4 + j];
#pragma unroll
            for (int i = 0; i < 4; i++)
#pragma unroll
                for (int j = 0; j < 4; j++)
                    o[i][j] = fmaf(pv[i], vv[j], o[i][j]);
        }
        __syncthreads();   // before next-iter tile loads overwrite KPs/Vs
    }

    // Epilogue: y[b, t, h*64 + d]
#pragma unroll
    for (int i = 0; i < 4; i++) {
        float inv = 1.f / lrow[i];
        int t = q0 + ty * 4 + i;
        size_t base = ((size_t)b * Tdim + t) * Cdim + h * Ddim + tx * 4;
        *(float4*)&y[base] =
            make_float4(o[i][0] * inv, o[i][1] * inv, o[i][2] * inv, o[i][3] * inv);
    }
}

// ---------------------------------------------------------------------------
extern "C" void kernel_launch(void* const* d_in, const int* in_sizes, int n_in,
                              void* d_out, int out_size)
{
    const float* x  = (const float*)d_in[0];   // hidden_states [B,T,C]
    const float* bw = (const float*)d_in[1];   // basis_w [R,C]
    const float* uf = (const float*)d_in[2];   // u_factor [H,R,S]
    const float* vf = (const float*)d_in[3];   // v_factor [H,R,S]
    const float* vw = (const float*)d_in[4];   // v_proj_w [C,C]
    const float* vb = (const float*)d_in[5];   // v_proj_b [C]
    const float* ow = (const float*)d_in[6];   // o_proj_w [C,C]
    const float* ob = (const float*)d_in[7];   // o_proj_b [C]
    float* out = (float*)d_out;

    float *latent, *q, *k, *v, *y;
    cudaGetSymbolAddress((void**)&latent, g_latent);
    cudaGetSymbolAddress((void**)&q, g_q);
    cudaGetSymbolAddress((void**)&k, g_k);
    cudaGetSymbolAddress((void**)&v, g_v);
    cudaGetSymbolAddress((void**)&y, g_y);

    // latent = x * basis_w^T    [8192,256]
    gemm_nt<0, false><<<dim3(Rdim / 64, Mrows / 128), 256>>>(x, bw, nullptr, latent, Rdim, Cdim);
    // q,k per head              [B,H,T,64]
    gemm_qk<<<dim3(Mrows / 64, Hdim), 256>>>(latent, uf, vf, q, k);
    // v = x * v_proj_w^T + b -> [B,H,T,64]
    gemm_nt<1, true><<<dim3(Cdim / 64, Mrows / 128), 256>>>(x, vw, vb, v, Cdim, Cdim);
    // causal flash attention -> y [B,T,C]
    flash_attn<<<dim3(Tdim / 64, Bdim * Hdim), 256>>>(q, k, v, y);
    // out = y * o_proj_w^T + b
    gemm_nt<0, true><<<dim3(Cdim / 64, Mrows / 128), 256>>>(y, ow, ob, out, Cdim, Cdim);
}